// round 16
// baseline (speedup 1.0000x reference)
#include <cuda_runtime.h>
#include <cuda_bf16.h>
#include <cstdint>

// ---------------------------------------------------------------------------
// GCNModelVAE forward — bf16 mma.sync GEMMs with 3-term error compensation.
// (tcgen05 unavailable: harness ptxas targets plain sm_103)
//   support = x @ Wh                  [8192,512]@[512,256]    split-K 2
//   hidden  = relu(adj @ support)     [8192,8192]@[8192,256]  split-K 8
//   s       = hidden @ [Wm|Wl]        [8192,256]@[256,128]    split-K 4
//   zcat    = adj @ s                 [8192,8192]@[8192,128]  split-K 16
//   recon   = z_mean @ z_mean^T       [8192,64] symmetric rank-k (upper CTAs)
// Output: [recon | z_mean | z_log_std]
//
// Compensation: a = ah + al (bf16 hi + bf16 residual);
//   C = Ah*Bl + Al*Bh + Ah*Bh   (Al*Bl ~2^-18 dropped) -> ~1e-5 per GEMM.
// R16 = R15 with the mma_block compile fix (acc[mt][nf] indexing). De-phase
// the warps: stagger (a) kk half-tile order by wid&1 and (b) Bl/Bh pass order
// by wid&2 — order-free work, so numerics stay ~identical.
// ---------------------------------------------------------------------------

#define NN   8192
#define DIN  512
#define DHID 256
#define DZ   64
#define DCAT 128

// ---- scratch (allocation-free) ----
#define SZ_PART     (16*NN*DCAT)
#define OFF_SUPPORT 0
#define OFF_HIDDEN  (OFF_SUPPORT + NN*DHID)
#define OFF_PART    (OFF_HIDDEN  + NN*DHID)
#define OFF_S       (OFF_PART    + SZ_PART)
#define OFF_WCAT    (OFF_S       + NN*DCAT)
#define SZ_TOTAL    (OFF_WCAT    + DHID*DCAT)

__device__ __align__(16) float g_scratch[SZ_TOTAL];

// ---------------------------------------------------------------------------
// helpers
// ---------------------------------------------------------------------------
__device__ __forceinline__ uint32_t smem_u32(const void* p) {
    uint32_t a;
    asm("{ .reg .u64 t; cvta.to.shared.u64 t, %1; cvt.u32.u64 %0, t; }"
        : "=r"(a) : "l"(p));
    return a;
}

__device__ __forceinline__ uint32_t pack_bf2(float lo, float hi) {
    uint32_t r;
    asm("cvt.rn.bf16x2.f32 %0, %1, %2;" : "=r"(r) : "f"(hi), "f"(lo));
    return r;
}

__device__ __forceinline__ void ldm_x4(uint32_t* r, uint32_t addr) {
    asm volatile("ldmatrix.sync.aligned.m8n8.x4.shared.b16 {%0,%1,%2,%3}, [%4];"
                 : "=r"(r[0]), "=r"(r[1]), "=r"(r[2]), "=r"(r[3]) : "r"(addr));
}

__device__ __forceinline__ void ldm_x4_t(uint32_t* r, uint32_t addr) {
    asm volatile("ldmatrix.sync.aligned.m8n8.x4.trans.shared.b16 {%0,%1,%2,%3}, [%4];"
                 : "=r"(r[0]), "=r"(r[1]), "=r"(r[2]), "=r"(r[3]) : "r"(addr));
}

__device__ __forceinline__ void mma_bf16(float* c, const uint32_t* a, const uint32_t* b) {
    asm volatile(
        "mma.sync.aligned.m16n8k16.row.col.f32.bf16.bf16.f32 "
        "{%0,%1,%2,%3}, {%4,%5,%6,%7}, {%8,%9}, {%0,%1,%2,%3};"
        : "+f"(c[0]), "+f"(c[1]), "+f"(c[2]), "+f"(c[3])
        : "r"(a[0]), "r"(a[1]), "r"(a[2]), "r"(a[3]), "r"(b[0]), "r"(b[1]));
}

__device__ __forceinline__ void split_pack(float4 v, uint2& hp, uint2& lp) {
    hp.x = pack_bf2(v.x, v.y);
    hp.y = pack_bf2(v.z, v.w);
    float h0 = __uint_as_float(hp.x << 16);
    float h1 = __uint_as_float(hp.x & 0xffff0000u);
    float h2 = __uint_as_float(hp.y << 16);
    float h3 = __uint_as_float(hp.y & 0xffff0000u);
    lp.x = pack_bf2(v.x - h0, v.y - h1);
    lp.y = pack_bf2(v.z - h2, v.w - h3);
}

__device__ __forceinline__ void cp_async16(uint32_t dst, const void* src) {
    asm volatile("cp.async.cg.shared.global [%0], [%1], 16;"
                 :: "r"(dst), "l"(src) : "memory");
}
#define CP_COMMIT() asm volatile("cp.async.commit_group;" ::: "memory")
#define CP_WAIT0()  asm volatile("cp.async.wait_group 0;" ::: "memory")

__device__ __forceinline__ float4 lds128(uint32_t a) {
    float4 v;
    asm volatile("ld.shared.v4.f32 {%0,%1,%2,%3}, [%4];"
                 : "=f"(v.x), "=f"(v.y), "=f"(v.z), "=f"(v.w) : "r"(a));
    return v;
}

// load 8 n8-fragments (one 64-col x k16 batch) via ldmatrix.trans
__device__ __forceinline__ void load_B8(uint32_t Bf[8][2], uint32_t base) {
#pragma unroll
    for (int nf2 = 0; nf2 < 4; nf2++) {
        uint32_t t[4];
        ldm_x4_t(t, base + (uint32_t)(nf2 * 32));
        Bf[2 * nf2][0] = t[0]; Bf[2 * nf2][1] = t[1];
        Bf[2 * nf2 + 1][0] = t[2]; Bf[2 * nf2 + 1][1] = t[3];
    }
}

__device__ __forceinline__ void mma_block(float acc[2][8][4], uint32_t A[2][4],
                                          uint32_t Bf[8][2]) {
#pragma unroll
    for (int mt = 0; mt < 2; mt++)
#pragma unroll
        for (int nf = 0; nf < 8; nf++)
            mma_bf16(acc[mt][nf], A[mt], Bf[nf]);
}

// ---------------------------------------------------------------------------
// smem layouts
// ---------------------------------------------------------------------------
#define PITCH   80                  // A bf16 tiles: [m][64B of k], 80B pitch
#define SEGSZ   (128 * PITCH)       // 10240
#define PITCHB  272                 // B bf16 tiles: [k][256B of n], 272B pitch
#define SEGB    (32 * PITCHB)       // 8704

// nmajor bf16 stage layout
#define N_AH    0
#define N_AL    (1 * SEGSZ)
#define N_BH    (2 * SEGSZ)
#define N_BL    (2 * SEGSZ + SEGB)
#define N_STAGE (2 * SEGSZ + 2 * SEGB)   // 37888
// fp32 cp.async staging (single buffer): A 128x128B, B 32x512B
#define STG_A   (2 * N_STAGE)            // 75776
#define STG_B   (STG_A + 16384)          // 92160
#define N_SMEM  (STG_B + 16384)          // 108544

// kmajor (syrk) stage layout — unchanged
#define SEG_AH  0
#define SEG_AL  (1 * SEGSZ)
#define SEG_BL  (2 * SEGSZ)
#define SEG_BH  (3 * SEGSZ)
#define GSTAGE  (4 * SEGSZ)              // 40960
#define K_SMEM  (2 * GSTAGE)             // 81920

// ---------------------------------------------------------------------------
// bf16x3 GEMM, B in natural [K,N] row-major: C = A[M,K] @ B[K,N].
// BM=BN=128, BK=32. 256 threads, warps 4(m) x 2(n), warp tile 32x64.
// cp.async fp32 staging issued one tile ahead; 2 bf16 stages; ONE barrier
// per k-tile; occupancy 2. Warp-staggered kk / pass order (de-phasing).
// grid=(N/128, M/128, K/kChunk).
// ---------------------------------------------------------------------------
__global__ void __launch_bounds__(256, 2)
bf16x3_gemm_bn(const float* __restrict__ A, const float* __restrict__ B,
               float* __restrict__ C, int M, int N, int K, int ldB, int kChunk)
{
    extern __shared__ __align__(16) char sm[];
    const uint32_t smb = smem_u32(sm);

    const int tid = threadIdx.x;
    const int wid = tid >> 5;
    const int lane = tid & 31;
    const int warp_m = wid & 3;
    const int warp_n = wid >> 2;

    const int m0 = blockIdx.y * 128;
    const int n0 = blockIdx.x * 128;
    const int kBeg = blockIdx.z * kChunk;
    const int nkt = kChunk >> 5;
    float* Cout = C + (size_t)blockIdx.z * (size_t)M * (size_t)N;

    float acc[2][8][4];
#pragma unroll
    for (int mt = 0; mt < 2; mt++)
#pragma unroll
        for (int nf = 0; nf < 8; nf++)
#pragma unroll
            for (int e = 0; e < 4; e++) acc[mt][nf][e] = 0.f;

    // A loader: thread -> (row = lr + 32i, k-float4 = c4)
    const int lr = tid >> 3;
    const int c4 = tid & 7;
    const float* Ab = A + (size_t)(m0 + lr) * (size_t)K + c4 * 4;
    const uint32_t stA = (uint32_t)(lr * PITCH + c4 * 8);
    const uint32_t sgA = smb + STG_A + (uint32_t)(lr * 128 + c4 * 16);

    // B loader: thread -> (k-row = kq, n-chunk = ncb + 8i)
    const int kq = tid >> 3;
    const int ncb = tid & 7;
    const float* Bb = B + (size_t)kq * (size_t)ldB + n0 + ncb * 4;
    const uint32_t stB = (uint32_t)(kq * PITCHB + ncb * 8);
    const uint32_t sgB = smb + STG_B + (uint32_t)(kq * 512 + ncb * 16);

    // ldmatrix fragment addresses
    const uint32_t a_row = (uint32_t)(warp_m * 32 + (lane & 15));
    const uint32_t a_off = a_row * PITCH + ((uint32_t)(lane >> 4) << 4);
    const uint32_t b_row = (uint32_t)((lane & 7) + ((lane >> 3) & 1) * 8);
    const uint32_t b_off = b_row * PITCHB + (uint32_t)warp_n * 128u
                         + (((uint32_t)lane >> 4) << 4);

    // de-phasing controls (order-free work, per-warp deterministic)
    const int kkx = wid & 1;             // kk traversal order
    const bool bhFirst = (wid & 2) != 0; // pass order within kk

    // prologue: stage tile 0
    {
        const int k0 = kBeg;
#pragma unroll
        for (int i = 0; i < 4; i++) {
            cp_async16(sgA + (uint32_t)(i * 32 * 128),
                       Ab + (size_t)(i * 32) * (size_t)K + k0);
            cp_async16(sgB + (uint32_t)(i * 128),
                       Bb + (size_t)k0 * (size_t)ldB + i * 32);
        }
        CP_COMMIT();
    }

    for (int kt = 0; kt < nkt; kt++) {
        const uint32_t stg = (uint32_t)(kt & 1) * N_STAGE;
        char* sp = sm + stg;

        // ---- staging ready (own chunks) -> convert -> bf16 tiles ----
        CP_WAIT0();
#pragma unroll
        for (int i = 0; i < 4; i++) {
            float4 va = lds128(sgA + (uint32_t)(i * 32 * 128));
            uint2 hp, lp;
            split_pack(va, hp, lp);
            const uint32_t offA = stA + (uint32_t)(i * 32 * PITCH);
            *(uint2*)(sp + N_AH + offA) = hp;
            *(uint2*)(sp + N_AL + offA) = lp;
            float4 vb = lds128(sgB + (uint32_t)(i * 128));
            split_pack(vb, hp, lp);
            const uint32_t offB = stB + (uint32_t)(i * 64);
            *(uint2*)(sp + N_BH + offB) = hp;
            *(uint2*)(sp + N_BL + offB) = lp;
        }
        __syncthreads();

        // ---- issue next tile's cp.async (hides under mma phase) ----
        if (kt + 1 < nkt) {
            const int k1 = kBeg + ((kt + 1) << 5);
#pragma unroll
            for (int i = 0; i < 4; i++) {
                cp_async16(sgA + (uint32_t)(i * 32 * 128),
                           Ab + (size_t)(i * 32) * (size_t)K + k1);
                cp_async16(sgB + (uint32_t)(i * 128),
                           Bb + (size_t)k1 * (size_t)ldB + i * 32);
            }
        }
        CP_COMMIT();

        // ---- compute: 2 k16 steps x 3 passes, warp-staggered order ----
        const uint32_t sa = smb + stg + a_off;
        const uint32_t sb = smb + stg + b_off;
#pragma unroll
        for (int kks = 0; kks < 2; kks++) {
            const int kk = kks ^ kkx;
            const uint32_t kbA = (uint32_t)(kk * 32);
            const uint32_t kbB = (uint32_t)(kk * 16 * PITCHB);
            uint32_t Ah[2][4], Al[2][4];
#pragma unroll
            for (int mt = 0; mt < 2; mt++) {
                const uint32_t base = sa + (uint32_t)(mt * 16 * PITCH) + kbA;
                ldm_x4(Ah[mt], base + N_AH);
                ldm_x4(Al[mt], base + N_AL);
            }
            uint32_t Bf[8][2];
            if (!bhFirst) {
                load_B8(Bf, sb + N_BL + kbB);
                mma_block(acc, Ah, Bf);
                load_B8(Bf, sb + N_BH + kbB);
                mma_block(acc, Al, Bf);
                mma_block(acc, Ah, Bf);
            } else {
                load_B8(Bf, sb + N_BH + kbB);
                mma_block(acc, Al, Bf);
                mma_block(acc, Ah, Bf);
                load_B8(Bf, sb + N_BL + kbB);
                mma_block(acc, Ah, Bf);
            }
        }
    }

    const int erow = m0 + warp_m * 32 + (lane >> 2);
    const int ecol = n0 + warp_n * 64 + 2 * (lane & 3);
#pragma unroll
    for (int mt = 0; mt < 2; mt++) {
#pragma unroll
        for (int nf = 0; nf < 8; nf++) {
            float* p0 = Cout + (size_t)(erow + mt * 16) * (size_t)N + ecol + nf * 8;
            float* p1 = p0 + (size_t)8 * (size_t)N;
            *(float2*)p0 = make_float2(acc[mt][nf][0], acc[mt][nf][1]);
            *(float2*)p1 = make_float2(acc[mt][nf][2], acc[mt][nf][3]);
        }
    }
}

// ---------------------------------------------------------------------------
// Symmetric rank-k (K-major path, unchanged): C = Z @ Z^T, upper CTAs only.
// ---------------------------------------------------------------------------
__global__ void __launch_bounds__(256, 2)
bf16x3_syrk(const float* __restrict__ Z, float* __restrict__ C)
{
    const int bi = blockIdx.y, bj = blockIdx.x;
    if (bj < bi) return;

    extern __shared__ __align__(16) char sm[];
    const uint32_t smb = smem_u32(sm);

    const int tid = threadIdx.x;
    const int wid = tid >> 5;
    const int lane = tid & 31;
    const int warp_m = wid & 3;
    const int warp_n = wid >> 2;

    const int m0 = bi * 128;
    const int n0 = bj * 128;
    const int K = DZ;

    float acc[2][8][4];
#pragma unroll
    for (int mt = 0; mt < 2; mt++)
#pragma unroll
        for (int nf = 0; nf < 8; nf++)
#pragma unroll
            for (int e = 0; e < 4; e++) acc[mt][nf][e] = 0.f;

    const int lr = tid >> 3;
    const int c4 = tid & 7;
    const float* Ab = Z + (size_t)(m0 + lr) * (size_t)K + c4 * 4;
    const float* Bb = Z + (size_t)(n0 + lr) * (size_t)K + c4 * 4;
    const uint32_t stoff = (uint32_t)(lr * PITCH + c4 * 8);

    const uint32_t a_row = (uint32_t)(warp_m * 32 + (lane & 15));
    const uint32_t a_off = a_row * PITCH + ((uint32_t)(lane >> 4) << 4);
    const uint32_t b_row = (uint32_t)(warp_n * 64 + (lane & 7) + ((lane >> 4) << 3));
    const uint32_t b_off = b_row * PITCH + (((uint32_t)(lane >> 3) & 1) << 4);

    for (int kt = 0; kt < 2; kt++) {
        const uint32_t stg = (uint32_t)(kt & 1) * GSTAGE;
        char* sp = sm + stg;
        const int k0 = kt << 5;
#pragma unroll
        for (int i = 0; i < 4; i++) {
            const uint32_t off = stoff + (uint32_t)(i * 32 * PITCH);
            float4 va = *(const float4*)(Ab + (size_t)(i * 32) * (size_t)K + k0);
            float4 vb = *(const float4*)(Bb + (size_t)(i * 32) * (size_t)K + k0);
            uint2 hp, lp;
            split_pack(va, hp, lp);
            *(uint2*)(sp + SEG_AH + off) = hp;
            *(uint2*)(sp + SEG_AL + off) = lp;
            split_pack(vb, hp, lp);
            *(uint2*)(sp + SEG_BH + off) = hp;
            *(uint2*)(sp + SEG_BL + off) = lp;
        }
        __syncthreads();
        const uint32_t sa = smb + stg + a_off;
        const uint32_t sb = smb + stg + b_off;
#pragma unroll
        for (int kk = 0; kk < 2; kk++) {
            const uint32_t kb = (uint32_t)(kk * 32);
            uint32_t Ah[2][4], Al[2][4];
#pragma unroll
            for (int mt = 0; mt < 2; mt++) {
                const uint32_t base = sa + (uint32_t)(mt * 16 * PITCH) + kb;
                ldm_x4(Ah[mt], base + SEG_AH);
                ldm_x4(Al[mt], base + SEG_AL);
            }
            uint32_t Bf[8][2];
#pragma unroll
            for (int nf2 = 0; nf2 < 4; nf2++) {
                uint32_t t[4];
                ldm_x4(t, sb + SEG_BL + (uint32_t)(nf2 * 16 * PITCH) + kb);
                Bf[2 * nf2][0] = t[0]; Bf[2 * nf2][1] = t[1];
                Bf[2 * nf2 + 1][0] = t[2]; Bf[2 * nf2 + 1][1] = t[3];
            }
#pragma unroll
            for (int mt = 0; mt < 2; mt++)
#pragma unroll
                for (int nf = 0; nf < 8; nf++)
                    mma_bf16(acc[mt][nf], Ah[mt], Bf[nf]);
#pragma unroll
            for (int nf2 = 0; nf2 < 4; nf2++) {
                uint32_t t[4];
                ldm_x4(t, sb + SEG_BH + (uint32_t)(nf2 * 16 * PITCH) + kb);
                Bf[2 * nf2][0] = t[0]; Bf[2 * nf2][1] = t[1];
                Bf[2 * nf2 + 1][0] = t[2]; Bf[2 * nf2 + 1][1] = t[3];
            }
#pragma unroll
            for (int mt = 0; mt < 2; mt++)
#pragma unroll
                for (int nf = 0; nf < 8; nf++) {
                    mma_bf16(acc[mt][nf], Al[mt], Bf[nf]);
                    mma_bf16(acc[mt][nf], Ah[mt], Bf[nf]);
                }
        }
    }

    const int erow0 = warp_m * 32 + (lane >> 2);
    const int ecol0 = warp_n * 64 + 2 * (lane & 3);
#pragma unroll
    for (int mt = 0; mt < 2; mt++) {
#pragma unroll
        for (int nf = 0; nf < 8; nf++) {
            float* p0 = C + (size_t)(m0 + erow0 + mt * 16) * (size_t)NN
                          + n0 + ecol0 + nf * 8;
            float* p1 = p0 + (size_t)8 * (size_t)NN;
            *(float2*)p0 = make_float2(acc[mt][nf][0], acc[mt][nf][1]);
            *(float2*)p1 = make_float2(acc[mt][nf][2], acc[mt][nf][3]);
        }
    }

    if (bi != bj) {
        __syncthreads();
        float* smT = (float*)sm;               // [128][132]
#pragma unroll
        for (int mt = 0; mt < 2; mt++)
#pragma unroll
            for (int nf = 0; nf < 8; nf++) {
                const int rr = erow0 + mt * 16;
                const int cc = ecol0 + nf * 8;
                smT[(cc + 0) * 132 + rr]     = acc[mt][nf][0];
                smT[(cc + 1) * 132 + rr]     = acc[mt][nf][1];
                smT[(cc + 0) * 132 + rr + 8] = acc[mt][nf][2];
                smT[(cc + 1) * 132 + rr + 8] = acc[mt][nf][3];
            }
        __syncthreads();
        const int r2 = tid >> 1;
        const int half = (tid & 1) * 64;
        float* dst = C + (size_t)(n0 + r2) * (size_t)NN + m0 + half;
        const float* src = smT + r2 * 132 + half;
#pragma unroll
        for (int j = 0; j < 16; j++)
            *(float4*)(dst + j * 4) = *(const float4*)(src + j * 4);
    }
}

// ---------------------------------------------------------------------------
// helpers: pack, reducers
// ---------------------------------------------------------------------------
__global__ void pack_wcat(const float* __restrict__ Wm, const float* __restrict__ Wl,
                          float* __restrict__ Wcat) {
    int i = blockIdx.x * blockDim.x + threadIdx.x;
    if (i >= DHID * DCAT) return;
    int k = i >> 7, c = i & 127;
    Wcat[i] = (c < DZ) ? Wm[k * DZ + c] : Wl[k * DZ + (c - DZ)];
}

template<int S, bool RELU>
__global__ void reduceN(const float* __restrict__ p, size_t stride,
                        float* __restrict__ out, int n4) {
    int base = blockIdx.x * (blockDim.x * 4) + threadIdx.x;
#pragma unroll
    for (int j = 0; j < 4; j++) {
        int i = base + j * 256;
        if (i >= n4) return;
        float4 r = ((const float4*)p)[i];
#pragma unroll
        for (int s = 1; s < S; s++) {
            float4 v = ((const float4*)(p + (size_t)s * stride))[i];
            r.x += v.x; r.y += v.y; r.z += v.z; r.w += v.w;
        }
        if (RELU) {
            r.x = fmaxf(r.x, 0.f); r.y = fmaxf(r.y, 0.f);
            r.z = fmaxf(r.z, 0.f); r.w = fmaxf(r.w, 0.f);
        }
        ((float4*)out)[i] = r;
    }
}

__global__ void reduce16_split(const float* __restrict__ p, size_t stride,
                               float* __restrict__ zm, float* __restrict__ zl) {
    int base = blockIdx.x * (blockDim.x * 4) + threadIdx.x;
#pragma unroll
    for (int j = 0; j < 4; j++) {
        int i = base + j * 256;
        if (i >= NN * DCAT / 4) return;
        int row = i >> 5, c4 = i & 31;
        float4 r = ((const float4*)p)[i];
#pragma unroll
        for (int s = 1; s < 16; s++) {
            float4 v = ((const float4*)(p + (size_t)s * stride))[i];
            r.x += v.x; r.y += v.y; r.z += v.z; r.w += v.w;
        }
        if (c4 < 16) ((float4*)zm)[(size_t)row * 16 + c4] = r;
        else         ((float4*)zl)[(size_t)row * 16 + (c4 - 16)] = r;
    }
}

// ---------------------------------------------------------------------------
extern "C" void kernel_launch(void* const* d_in, const int* in_sizes, int n_in,
                              void* d_out, int out_size) {
    const float* x = nullptr;
    const float* adj = nullptr;
    const float* Wh = nullptr;
    const float* Wsmall[2] = {nullptr, nullptr};
    int nsmall = 0;
    for (int i = 0; i < n_in; i++) {
        const float* p = (const float*)d_in[i];
        switch (in_sizes[i]) {
            case NN * DIN:   x = p; break;
            case NN * NN:    adj = p; break;
            case DIN * DHID: Wh = p; break;
            case DHID * DZ:  if (nsmall < 2) Wsmall[nsmall++] = p; break;
            default: break;
        }
    }
    const float* Wm = Wsmall[0];
    const float* Wl = Wsmall[1];

    float* out = (float*)d_out;
    float* recon = out;
    float* zm = out + (size_t)NN * (size_t)NN;
    float* zl = zm + (size_t)NN * (size_t)DZ;

    float* ws = nullptr;
    cudaGetSymbolAddress((void**)&ws, g_scratch);
    float* support = ws + OFF_SUPPORT;
    float* hidden  = ws + OFF_HIDDEN;
    float* part    = ws + OFF_PART;
    float* sbuf    = ws + OFF_S;
    float* wcat    = ws + OFF_WCAT;

    cudaFuncSetAttribute(bf16x3_gemm_bn, cudaFuncAttributeMaxDynamicSharedMemorySize,
                         N_SMEM);
    cudaFuncSetAttribute(bf16x3_syrk, cudaFuncAttributeMaxDynamicSharedMemorySize,
                         K_SMEM);

    pack_wcat<<<(DHID * DCAT + 255) / 256, 256>>>(Wm, Wl, wcat);

    // support = x @ Wh, split-K 2
    bf16x3_gemm_bn<<<dim3(2, 64, 2), 256, N_SMEM>>>(x, Wh, part, NN, DHID, DIN,
                                                    DHID, DIN / 2);
    reduceN<2, false><<<(NN * DHID / 4 + 1023) / 1024, 256>>>(part, (size_t)NN * DHID,
                                                              support, NN * DHID / 4);

    // hidden = relu(adj @ support), split-K 8
    bf16x3_gemm_bn<<<dim3(2, 64, 8), 256, N_SMEM>>>(adj, support, part, NN, DHID, NN,
                                                    DHID, NN / 8);
    reduceN<8, true><<<(NN * DHID / 4 + 1023) / 1024, 256>>>(part, (size_t)NN * DHID,
                                                             hidden, NN * DHID / 4);

    // s = hidden @ [Wm|Wl], split-K 4
    bf16x3_gemm_bn<<<dim3(1, 64, 4), 256, N_SMEM>>>(hidden, wcat, part, NN, DCAT, DHID,
                                                    DCAT, DHID / 4);
    reduceN<4, false><<<(NN * DCAT / 4 + 1023) / 1024, 256>>>(part, (size_t)NN * DCAT,
                                                              sbuf, NN * DCAT / 4);

    // zcat = adj @ s, split-K 16 -> z_mean, z_log_std
    bf16x3_gemm_bn<<<dim3(1, 64, 16), 256, N_SMEM>>>(adj, sbuf, part, NN, DCAT, NN,
                                                     DCAT, NN / 16);
    reduce16_split<<<(NN * DCAT / 4 + 1023) / 1024, 256>>>(part, (size_t)NN * DCAT,
                                                           zm, zl);

    // recon = z_mean @ z_mean^T (symmetric)
    bf16x3_syrk<<<dim3(64, 64), 256, K_SMEM>>>(zm, recon);
}

// round 17
// speedup vs baseline: 1.0153x; 1.0153x over previous
#include <cuda_runtime.h>
#include <cuda_bf16.h>
#include <cstdint>

// ---------------------------------------------------------------------------
// GCNModelVAE forward — bf16 mma.sync GEMMs with 3-term error compensation.
// (tcgen05 unavailable: harness ptxas targets plain sm_103)
//   support = x @ Wh                  [8192,512]@[512,256]    split-K 2
//   hidden  = relu(adj @ support)     [8192,8192]@[8192,256]  split-K 8
//   s       = hidden @ [Wm|Wl]        [8192,256]@[256,128]    split-K 4
//   zcat    = adj @ s                 [8192,8192]@[8192,128]  split-K 16
//   recon   = z_mean @ z_mean^T       [8192,64] symmetric rank-k (upper CTAs)
// Output: [recon | z_mean | z_log_std]
//
// Compensation: a = ah + al (bf16 hi + bf16 residual);
//   C = Ah*Bl + Al*Bh + Ah*Bh   (Al*Bl ~2^-18 dropped) -> ~1e-5 per GEMM.
// R17 = R13 (561us best; de-phasing falsified) + safe trims:
//   - cp.async for tile kt+1 issued BEFORE the barrier (own-chunk staging
//     refill is race-free; DMA gets a barrier's head start)
//   - reducers do 8 float4/thread (were latency-bound at ~3.5 TB/s)
// Mainloop math identical to R13 -> rel_err must be exactly 1.162501e-05.
// ---------------------------------------------------------------------------

#define NN   8192
#define DIN  512
#define DHID 256
#define DZ   64
#define DCAT 128

// ---- scratch (allocation-free) ----
#define SZ_PART     (16*NN*DCAT)
#define OFF_SUPPORT 0
#define OFF_HIDDEN  (OFF_SUPPORT + NN*DHID)
#define OFF_PART    (OFF_HIDDEN  + NN*DHID)
#define OFF_S       (OFF_PART    + SZ_PART)
#define OFF_WCAT    (OFF_S       + NN*DCAT)
#define SZ_TOTAL    (OFF_WCAT    + DHID*DCAT)

__device__ __align__(16) float g_scratch[SZ_TOTAL];

// ---------------------------------------------------------------------------
// helpers
// ---------------------------------------------------------------------------
__device__ __forceinline__ uint32_t smem_u32(const void* p) {
    uint32_t a;
    asm("{ .reg .u64 t; cvta.to.shared.u64 t, %1; cvt.u32.u64 %0, t; }"
        : "=r"(a) : "l"(p));
    return a;
}

__device__ __forceinline__ uint32_t pack_bf2(float lo, float hi) {
    uint32_t r;
    asm("cvt.rn.bf16x2.f32 %0, %1, %2;" : "=r"(r) : "f"(hi), "f"(lo));
    return r;
}

__device__ __forceinline__ void ldm_x4(uint32_t* r, uint32_t addr) {
    asm volatile("ldmatrix.sync.aligned.m8n8.x4.shared.b16 {%0,%1,%2,%3}, [%4];"
                 : "=r"(r[0]), "=r"(r[1]), "=r"(r[2]), "=r"(r[3]) : "r"(addr));
}

__device__ __forceinline__ void ldm_x4_t(uint32_t* r, uint32_t addr) {
    asm volatile("ldmatrix.sync.aligned.m8n8.x4.trans.shared.b16 {%0,%1,%2,%3}, [%4];"
                 : "=r"(r[0]), "=r"(r[1]), "=r"(r[2]), "=r"(r[3]) : "r"(addr));
}

__device__ __forceinline__ void mma_bf16(float* c, const uint32_t* a, const uint32_t* b) {
    asm volatile(
        "mma.sync.aligned.m16n8k16.row.col.f32.bf16.bf16.f32 "
        "{%0,%1,%2,%3}, {%4,%5,%6,%7}, {%8,%9}, {%0,%1,%2,%3};"
        : "+f"(c[0]), "+f"(c[1]), "+f"(c[2]), "+f"(c[3])
        : "r"(a[0]), "r"(a[1]), "r"(a[2]), "r"(a[3]), "r"(b[0]), "r"(b[1]));
}

__device__ __forceinline__ void split_pack(float4 v, uint2& hp, uint2& lp) {
    hp.x = pack_bf2(v.x, v.y);
    hp.y = pack_bf2(v.z, v.w);
    float h0 = __uint_as_float(hp.x << 16);
    float h1 = __uint_as_float(hp.x & 0xffff0000u);
    float h2 = __uint_as_float(hp.y << 16);
    float h3 = __uint_as_float(hp.y & 0xffff0000u);
    lp.x = pack_bf2(v.x - h0, v.y - h1);
    lp.y = pack_bf2(v.z - h2, v.w - h3);
}

__device__ __forceinline__ void cp_async16(uint32_t dst, const void* src) {
    asm volatile("cp.async.cg.shared.global [%0], [%1], 16;"
                 :: "r"(dst), "l"(src) : "memory");
}
#define CP_COMMIT() asm volatile("cp.async.commit_group;" ::: "memory")
#define CP_WAIT0()  asm volatile("cp.async.wait_group 0;" ::: "memory")

__device__ __forceinline__ float4 lds128(uint32_t a) {
    float4 v;
    asm volatile("ld.shared.v4.f32 {%0,%1,%2,%3}, [%4];"
                 : "=f"(v.x), "=f"(v.y), "=f"(v.z), "=f"(v.w) : "r"(a));
    return v;
}

// ---------------------------------------------------------------------------
// smem layouts
// ---------------------------------------------------------------------------
#define PITCH   80                  // A bf16 tiles: [m][64B of k], 80B pitch
#define SEGSZ   (128 * PITCH)       // 10240
#define PITCHB  272                 // B bf16 tiles: [k][256B of n], 272B pitch
#define SEGB    (32 * PITCHB)       // 8704

// nmajor bf16 stage layout
#define N_AH    0
#define N_AL    (1 * SEGSZ)
#define N_BH    (2 * SEGSZ)
#define N_BL    (2 * SEGSZ + SEGB)
#define N_STAGE (2 * SEGSZ + 2 * SEGB)   // 37888
// fp32 cp.async staging (single buffer): A 128x128B, B 32x512B
#define STG_A   (2 * N_STAGE)            // 75776
#define STG_B   (STG_A + 16384)          // 92160
#define N_SMEM  (STG_B + 16384)          // 108544

// kmajor (syrk) stage layout — unchanged
#define SEG_AH  0
#define SEG_AL  (1 * SEGSZ)
#define SEG_BL  (2 * SEGSZ)
#define SEG_BH  (3 * SEGSZ)
#define GSTAGE  (4 * SEGSZ)              // 40960
#define K_SMEM  (2 * GSTAGE)             // 81920

// ---------------------------------------------------------------------------
// bf16x3 GEMM, B in natural [K,N] row-major: C = A[M,K] @ B[K,N].
// BM=BN=128, BK=32. 256 threads, warps 4(m) x 2(n), warp tile 32x64.
// cp.async fp32 staging issued one tile ahead (pre-barrier); 2 bf16 stages;
// ONE barrier per k-tile; occupancy 2. grid=(N/128, M/128, K/kChunk).
// ---------------------------------------------------------------------------
__global__ void __launch_bounds__(256, 2)
bf16x3_gemm_bn(const float* __restrict__ A, const float* __restrict__ B,
               float* __restrict__ C, int M, int N, int K, int ldB, int kChunk)
{
    extern __shared__ __align__(16) char sm[];
    const uint32_t smb = smem_u32(sm);

    const int tid = threadIdx.x;
    const int wid = tid >> 5;
    const int lane = tid & 31;
    const int warp_m = wid & 3;
    const int warp_n = wid >> 2;

    const int m0 = blockIdx.y * 128;
    const int n0 = blockIdx.x * 128;
    const int kBeg = blockIdx.z * kChunk;
    const int nkt = kChunk >> 5;
    float* Cout = C + (size_t)blockIdx.z * (size_t)M * (size_t)N;

    float acc[2][8][4];
#pragma unroll
    for (int mt = 0; mt < 2; mt++)
#pragma unroll
        for (int nf = 0; nf < 8; nf++)
#pragma unroll
            for (int e = 0; e < 4; e++) acc[mt][nf][e] = 0.f;

    // A loader: thread -> (row = lr + 32i, k-float4 = c4)
    const int lr = tid >> 3;
    const int c4 = tid & 7;
    const float* Ab = A + (size_t)(m0 + lr) * (size_t)K + c4 * 4;
    const uint32_t stA = (uint32_t)(lr * PITCH + c4 * 8);
    const uint32_t sgA = smb + STG_A + (uint32_t)(lr * 128 + c4 * 16);

    // B loader: thread -> (k-row = kq, n-chunk = ncb + 8i)
    const int kq = tid >> 3;
    const int ncb = tid & 7;
    const float* Bb = B + (size_t)kq * (size_t)ldB + n0 + ncb * 4;
    const uint32_t stB = (uint32_t)(kq * PITCHB + ncb * 8);
    const uint32_t sgB = smb + STG_B + (uint32_t)(kq * 512 + ncb * 16);

    // ldmatrix fragment addresses
    const uint32_t a_row = (uint32_t)(warp_m * 32 + (lane & 15));
    const uint32_t a_off = a_row * PITCH + ((uint32_t)(lane >> 4) << 4);
    const uint32_t b_row = (uint32_t)((lane & 7) + ((lane >> 3) & 1) * 8);
    const uint32_t b_off = b_row * PITCHB + (uint32_t)warp_n * 128u
                         + (((uint32_t)lane >> 4) << 4);

    // prologue: stage tile 0
    {
        const int k0 = kBeg;
#pragma unroll
        for (int i = 0; i < 4; i++) {
            cp_async16(sgA + (uint32_t)(i * 32 * 128),
                       Ab + (size_t)(i * 32) * (size_t)K + k0);
            cp_async16(sgB + (uint32_t)(i * 128),
                       Bb + (size_t)k0 * (size_t)ldB + i * 32);
        }
        CP_COMMIT();
    }

    for (int kt = 0; kt < nkt; kt++) {
        const uint32_t stg = (uint32_t)(kt & 1) * N_STAGE;
        char* sp = sm + stg;

        // ---- staging ready (own chunks) -> convert -> bf16 tiles ----
        CP_WAIT0();
#pragma unroll
        for (int i = 0; i < 4; i++) {
            float4 va = lds128(sgA + (uint32_t)(i * 32 * 128));
            uint2 hp, lp;
            split_pack(va, hp, lp);
            const uint32_t offA = stA + (uint32_t)(i * 32 * PITCH);
            *(uint2*)(sp + N_AH + offA) = hp;
            *(uint2*)(sp + N_AL + offA) = lp;
            float4 vb = lds128(sgB + (uint32_t)(i * 128));
            split_pack(vb, hp, lp);
            const uint32_t offB = stB + (uint32_t)(i * 64);
            *(uint2*)(sp + N_BH + offB) = hp;
            *(uint2*)(sp + N_BL + offB) = lp;
        }

        // ---- issue next tile's cp.async BEFORE the barrier ----
        // Safe: each thread only refills staging chunks it itself just read
        // (LDS values already consumed into registers above).
        if (kt + 1 < nkt) {
            const int k1 = kBeg + ((kt + 1) << 5);
#pragma unroll
            for (int i = 0; i < 4; i++) {
                cp_async16(sgA + (uint32_t)(i * 32 * 128),
                           Ab + (size_t)(i * 32) * (size_t)K + k1);
                cp_async16(sgB + (uint32_t)(i * 128),
                           Bb + (size_t)k1 * (size_t)ldB + i * 32);
            }
        }
        CP_COMMIT();
        __syncthreads();

        // ---- compute: 2 k16 steps x 3 compensation passes ----
        const uint32_t sa = smb + stg + a_off;
        const uint32_t sb = smb + stg + b_off;
#pragma unroll
        for (int kk = 0; kk < 2; kk++) {
            const uint32_t kbA = (uint32_t)(kk * 32);
            const uint32_t kbB = (uint32_t)(kk * 16 * PITCHB);
            uint32_t Ah[2][4], Al[2][4];
#pragma unroll
            for (int mt = 0; mt < 2; mt++) {
                const uint32_t base = sa + (uint32_t)(mt * 16 * PITCH) + kbA;
                ldm_x4(Ah[mt], base + N_AH);
                ldm_x4(Al[mt], base + N_AL);
            }
            uint32_t Bf[8][2];
#pragma unroll
            for (int nf2 = 0; nf2 < 4; nf2++) {
                uint32_t t[4];
                ldm_x4_t(t, sb + N_BL + (uint32_t)(nf2 * 32) + kbB);
                Bf[2 * nf2][0] = t[0]; Bf[2 * nf2][1] = t[1];
                Bf[2 * nf2 + 1][0] = t[2]; Bf[2 * nf2 + 1][1] = t[3];
            }
#pragma unroll
            for (int mt = 0; mt < 2; mt++)
#pragma unroll
                for (int nf = 0; nf < 8; nf++)
                    mma_bf16(acc[mt][nf], Ah[mt], Bf[nf]);
#pragma unroll
            for (int nf2 = 0; nf2 < 4; nf2++) {
                uint32_t t[4];
                ldm_x4_t(t, sb + N_BH + (uint32_t)(nf2 * 32) + kbB);
                Bf[2 * nf2][0] = t[0]; Bf[2 * nf2][1] = t[1];
                Bf[2 * nf2 + 1][0] = t[2]; Bf[2 * nf2 + 1][1] = t[3];
            }
#pragma unroll
            for (int mt = 0; mt < 2; mt++)
#pragma unroll
                for (int nf = 0; nf < 8; nf++) {
                    mma_bf16(acc[mt][nf], Al[mt], Bf[nf]);
                    mma_bf16(acc[mt][nf], Ah[mt], Bf[nf]);
                }
        }
    }

    const int erow = m0 + warp_m * 32 + (lane >> 2);
    const int ecol = n0 + warp_n * 64 + 2 * (lane & 3);
#pragma unroll
    for (int mt = 0; mt < 2; mt++) {
#pragma unroll
        for (int nf = 0; nf < 8; nf++) {
            float* p0 = Cout + (size_t)(erow + mt * 16) * (size_t)N + ecol + nf * 8;
            float* p1 = p0 + (size_t)8 * (size_t)N;
            *(float2*)p0 = make_float2(acc[mt][nf][0], acc[mt][nf][1]);
            *(float2*)p1 = make_float2(acc[mt][nf][2], acc[mt][nf][3]);
        }
    }
}

// ---------------------------------------------------------------------------
// Symmetric rank-k (K-major path, unchanged): C = Z @ Z^T, upper CTAs only.
// ---------------------------------------------------------------------------
__global__ void __launch_bounds__(256, 2)
bf16x3_syrk(const float* __restrict__ Z, float* __restrict__ C)
{
    const int bi = blockIdx.y, bj = blockIdx.x;
    if (bj < bi) return;

    extern __shared__ __align__(16) char sm[];
    const uint32_t smb = smem_u32(sm);

    const int tid = threadIdx.x;
    const int wid = tid >> 5;
    const int lane = tid & 31;
    const int warp_m = wid & 3;
    const int warp_n = wid >> 2;

    const int m0 = bi * 128;
    const int n0 = bj * 128;
    const int K = DZ;

    float acc[2][8][4];
#pragma unroll
    for (int mt = 0; mt < 2; mt++)
#pragma unroll
        for (int nf = 0; nf < 8; nf++)
#pragma unroll
            for (int e = 0; e < 4; e++) acc[mt][nf][e] = 0.f;

    const int lr = tid >> 3;
    const int c4 = tid & 7;
    const float* Ab = Z + (size_t)(m0 + lr) * (size_t)K + c4 * 4;
    const float* Bb = Z + (size_t)(n0 + lr) * (size_t)K + c4 * 4;
    const uint32_t stoff = (uint32_t)(lr * PITCH + c4 * 8);

    const uint32_t a_row = (uint32_t)(warp_m * 32 + (lane & 15));
    const uint32_t a_off = a_row * PITCH + ((uint32_t)(lane >> 4) << 4);
    const uint32_t b_row = (uint32_t)(warp_n * 64 + (lane & 7) + ((lane >> 4) << 3));
    const uint32_t b_off = b_row * PITCH + (((uint32_t)(lane >> 3) & 1) << 4);

    for (int kt = 0; kt < 2; kt++) {
        const uint32_t stg = (uint32_t)(kt & 1) * GSTAGE;
        char* sp = sm + stg;
        const int k0 = kt << 5;
#pragma unroll
        for (int i = 0; i < 4; i++) {
            const uint32_t off = stoff + (uint32_t)(i * 32 * PITCH);
            float4 va = *(const float4*)(Ab + (size_t)(i * 32) * (size_t)K + k0);
            float4 vb = *(const float4*)(Bb + (size_t)(i * 32) * (size_t)K + k0);
            uint2 hp, lp;
            split_pack(va, hp, lp);
            *(uint2*)(sp + SEG_AH + off) = hp;
            *(uint2*)(sp + SEG_AL + off) = lp;
            split_pack(vb, hp, lp);
            *(uint2*)(sp + SEG_BH + off) = hp;
            *(uint2*)(sp + SEG_BL + off) = lp;
        }
        __syncthreads();
        const uint32_t sa = smb + stg + a_off;
        const uint32_t sb = smb + stg + b_off;
#pragma unroll
        for (int kk = 0; kk < 2; kk++) {
            const uint32_t kb = (uint32_t)(kk * 32);
            uint32_t Ah[2][4], Al[2][4];
#pragma unroll
            for (int mt = 0; mt < 2; mt++) {
                const uint32_t base = sa + (uint32_t)(mt * 16 * PITCH) + kb;
                ldm_x4(Ah[mt], base + SEG_AH);
                ldm_x4(Al[mt], base + SEG_AL);
            }
            uint32_t Bf[8][2];
#pragma unroll
            for (int nf2 = 0; nf2 < 4; nf2++) {
                uint32_t t[4];
                ldm_x4(t, sb + SEG_BL + (uint32_t)(nf2 * 16 * PITCH) + kb);
                Bf[2 * nf2][0] = t[0]; Bf[2 * nf2][1] = t[1];
                Bf[2 * nf2 + 1][0] = t[2]; Bf[2 * nf2 + 1][1] = t[3];
            }
#pragma unroll
            for (int mt = 0; mt < 2; mt++)
#pragma unroll
                for (int nf = 0; nf < 8; nf++)
                    mma_bf16(acc[mt][nf], Ah[mt], Bf[nf]);
#pragma unroll
            for (int nf2 = 0; nf2 < 4; nf2++) {
                uint32_t t[4];
                ldm_x4(t, sb + SEG_BH + (uint32_t)(nf2 * 16 * PITCH) + kb);
                Bf[2 * nf2][0] = t[0]; Bf[2 * nf2][1] = t[1];
                Bf[2 * nf2 + 1][0] = t[2]; Bf[2 * nf2 + 1][1] = t[3];
            }
#pragma unroll
            for (int mt = 0; mt < 2; mt++)
#pragma unroll
                for (int nf = 0; nf < 8; nf++) {
                    mma_bf16(acc[mt][nf], Al[mt], Bf[nf]);
                    mma_bf16(acc[mt][nf], Ah[mt], Bf[nf]);
                }
        }
    }

    const int erow0 = warp_m * 32 + (lane >> 2);
    const int ecol0 = warp_n * 64 + 2 * (lane & 3);
#pragma unroll
    for (int mt = 0; mt < 2; mt++) {
#pragma unroll
        for (int nf = 0; nf < 8; nf++) {
            float* p0 = C + (size_t)(m0 + erow0 + mt * 16) * (size_t)NN
                          + n0 + ecol0 + nf * 8;
            float* p1 = p0 + (size_t)8 * (size_t)NN;
            *(float2*)p0 = make_float2(acc[mt][nf][0], acc[mt][nf][1]);
            *(float2*)p1 = make_float2(acc[mt][nf][2], acc[mt][nf][3]);
        }
    }

    if (bi != bj) {
        __syncthreads();
        float* smT = (float*)sm;               // [128][132]
#pragma unroll
        for (int mt = 0; mt < 2; mt++)
#pragma unroll
            for (int nf = 0; nf < 8; nf++) {
                const int rr = erow0 + mt * 16;
                const int cc = ecol0 + nf * 8;
                smT[(cc + 0) * 132 + rr]     = acc[mt][nf][0];
                smT[(cc + 1) * 132 + rr]     = acc[mt][nf][1];
                smT[(cc + 0) * 132 + rr + 8] = acc[mt][nf][2];
                smT[(cc + 1) * 132 + rr + 8] = acc[mt][nf][3];
            }
        __syncthreads();
        const int r2 = tid >> 1;
        const int half = (tid & 1) * 64;
        float* dst = C + (size_t)(n0 + r2) * (size_t)NN + m0 + half;
        const float* src = smT + r2 * 132 + half;
#pragma unroll
        for (int j = 0; j < 16; j++)
            *(float4*)(dst + j * 4) = *(const float4*)(src + j * 4);
    }
}

// ---------------------------------------------------------------------------
// helpers: pack, reducers (8 float4 per thread)
// ---------------------------------------------------------------------------
__global__ void pack_wcat(const float* __restrict__ Wm, const float* __restrict__ Wl,
                          float* __restrict__ Wcat) {
    int i = blockIdx.x * blockDim.x + threadIdx.x;
    if (i >= DHID * DCAT) return;
    int k = i >> 7, c = i & 127;
    Wcat[i] = (c < DZ) ? Wm[k * DZ + c] : Wl[k * DZ + (c - DZ)];
}

template<int S, bool RELU>
__global__ void reduceN(const float* __restrict__ p, size_t stride,
                        float* __restrict__ out, int n4) {
    int base = blockIdx.x * (blockDim.x * 8) + threadIdx.x;
#pragma unroll
    for (int j = 0; j < 8; j++) {
        int i = base + j * 256;
        if (i >= n4) return;
        float4 r = ((const float4*)p)[i];
#pragma unroll
        for (int s = 1; s < S; s++) {
            float4 v = ((const float4*)(p + (size_t)s * stride))[i];
            r.x += v.x; r.y += v.y; r.z += v.z; r.w += v.w;
        }
        if (RELU) {
            r.x = fmaxf(r.x, 0.f); r.y = fmaxf(r.y, 0.f);
            r.z = fmaxf(r.z, 0.f); r.w = fmaxf(r.w, 0.f);
        }
        ((float4*)out)[i] = r;
    }
}

__global__ void reduce16_split(const float* __restrict__ p, size_t stride,
                               float* __restrict__ zm, float* __restrict__ zl) {
    int base = blockIdx.x * (blockDim.x * 8) + threadIdx.x;
#pragma unroll
    for (int j = 0; j < 8; j++) {
        int i = base + j * 256;
        if (i >= NN * DCAT / 4) return;
        int row = i >> 5, c4 = i & 31;
        float4 r = ((const float4*)p)[i];
#pragma unroll
        for (int s = 1; s < 16; s++) {
            float4 v = ((const float4*)(p + (size_t)s * stride))[i];
            r.x += v.x; r.y += v.y; r.z += v.z; r.w += v.w;
        }
        if (c4 < 16) ((float4*)zm)[(size_t)row * 16 + c4] = r;
        else         ((float4*)zl)[(size_t)row * 16 + (c4 - 16)] = r;
    }
}

// ---------------------------------------------------------------------------
extern "C" void kernel_launch(void* const* d_in, const int* in_sizes, int n_in,
                              void* d_out, int out_size) {
    const float* x = nullptr;
    const float* adj = nullptr;
    const float* Wh = nullptr;
    const float* Wsmall[2] = {nullptr, nullptr};
    int nsmall = 0;
    for (int i = 0; i < n_in; i++) {
        const float* p = (const float*)d_in[i];
        switch (in_sizes[i]) {
            case NN * DIN:   x = p; break;
            case NN * NN:    adj = p; break;
            case DIN * DHID: Wh = p; break;
            case DHID * DZ:  if (nsmall < 2) Wsmall[nsmall++] = p; break;
            default: break;
        }
    }
    const float* Wm = Wsmall[0];
    const float* Wl = Wsmall[1];

    float* out = (float*)d_out;
    float* recon = out;
    float* zm = out + (size_t)NN * (size_t)NN;
    float* zl = zm + (size_t)NN * (size_t)DZ;

    float* ws = nullptr;
    cudaGetSymbolAddress((void**)&ws, g_scratch);
    float* support = ws + OFF_SUPPORT;
    float* hidden  = ws + OFF_HIDDEN;
    float* part    = ws + OFF_PART;
    float* sbuf    = ws + OFF_S;
    float* wcat    = ws + OFF_WCAT;

    cudaFuncSetAttribute(bf16x3_gemm_bn, cudaFuncAttributeMaxDynamicSharedMemorySize,
                         N_SMEM);
    cudaFuncSetAttribute(bf16x3_syrk, cudaFuncAttributeMaxDynamicSharedMemorySize,
                         K_SMEM);

    pack_wcat<<<(DHID * DCAT + 255) / 256, 256>>>(Wm, Wl, wcat);

    // support = x @ Wh, split-K 2
    bf16x3_gemm_bn<<<dim3(2, 64, 2), 256, N_SMEM>>>(x, Wh, part, NN, DHID, DIN,
                                                    DHID, DIN / 2);
    reduceN<2, false><<<(NN * DHID / 4 + 2047) / 2048, 256>>>(part, (size_t)NN * DHID,
                                                              support, NN * DHID / 4);

    // hidden = relu(adj @ support), split-K 8
    bf16x3_gemm_bn<<<dim3(2, 64, 8), 256, N_SMEM>>>(adj, support, part, NN, DHID, NN,
                                                    DHID, NN / 8);
    reduceN<8, true><<<(NN * DHID / 4 + 2047) / 2048, 256>>>(part, (size_t)NN * DHID,
                                                             hidden, NN * DHID / 4);

    // s = hidden @ [Wm|Wl], split-K 4
    bf16x3_gemm_bn<<<dim3(1, 64, 4), 256, N_SMEM>>>(hidden, wcat, part, NN, DCAT, DHID,
                                                    DCAT, DHID / 4);
    reduceN<4, false><<<(NN * DCAT / 4 + 2047) / 2048, 256>>>(part, (size_t)NN * DCAT,
                                                              sbuf, NN * DCAT / 4);

    // zcat = adj @ s, split-K 16 -> z_mean, z_log_std
    bf16x3_gemm_bn<<<dim3(1, 64, 16), 256, N_SMEM>>>(adj, sbuf, part, NN, DCAT, NN,
                                                     DCAT, NN / 16);
    reduce16_split<<<(NN * DCAT / 4 + 2047) / 2048, 256>>>(part, (size_t)NN * DCAT,
                                                           zm, zl);

    // recon = z_mean @ z_mean^T (symmetric)
    bf16x3_syrk<<<dim3(64, 64), 256, K_SMEM>>>(zm, recon);
}